// round 6
// baseline (speedup 1.0000x reference)
#include <cuda_runtime.h>
#include <math.h>
#include <stdint.h>

#define T_STEPS 1024
#define BATCH   64
#define VDIM    256
#define HIDDEN  512
#define CPB     64                 // columns per CTA
#define BG      4                  // batches per group (= per cluster)
#define CBLKS   (HIDDEN / CPB)     // 8 CTAs per cluster
#define GROUPS  (BATCH / BG)       // 16 clusters
#define NB      (CBLKS * GROUPS)   // 128 CTAs
#define RT      256
#define WPAD    516                // Wh smem row stride (floats)
#define HPAD    520                // h smem row stride (floats)
// smem: Whs + 2 h buffers + mbarrier slot (16 floats for alignment/padding)
#define REC_SMEM ((CPB * WPAD + 2 * BG * HPAD + 16) * 4)

// Scratch (device globals: allocation APIs are forbidden)
__device__ float g_P [(size_t)T_STEPS * BATCH * HIDDEN];
__device__ float g_S0[(size_t)T_STEPS * BATCH * HIDDEN];

// packed f32x2 fma: acc.lo += w.lo*h.lo ; acc.hi += w.hi*h.hi
#define FMA2(acc, w, h) \
    asm("fma.rn.f32x2 %0, %1, %2, %0;" : "+l"(acc) : "l"(w), "l"(h))

__device__ __forceinline__ unsigned smem_u32(const void* p) {
    return (unsigned)__cvta_generic_to_shared(p);
}

// ---------------------------------------------------------------------------
// GEMM: C[m][n] = sum_k A[m][k]*W[n*ldw+k] + bias[n], C row stride = HIDDEN
// ---------------------------------------------------------------------------
__global__ __launch_bounds__(256) void gemm_awt(
    const float* __restrict__ A, const float* __restrict__ W,
    const float* __restrict__ bias, float* __restrict__ C,
    int K, int ldw)
{
    __shared__ float As[8][128];
    __shared__ float Ws[8][128];

    const int tid = threadIdx.x;
    const int m0 = blockIdx.y * 128;
    const int n0 = blockIdx.x * 128;
    const int tx = tid & 15;
    const int ty = tid >> 4;
    const int rowL = tid >> 1;
    const int colL = (tid & 1) * 4;

    const float* Ag = A + (size_t)(m0 + rowL) * K + colL;
    const float* Wg = W + (size_t)(n0 + rowL) * ldw + colL;

    float acc[8][8];
#pragma unroll
    for (int i = 0; i < 8; ++i)
#pragma unroll
        for (int j = 0; j < 8; ++j) acc[i][j] = 0.f;

    float4 av = *(const float4*)(Ag);
    float4 wv = *(const float4*)(Wg);

    for (int k0 = 0; k0 < K; k0 += 8) {
        __syncthreads();
        As[colL + 0][rowL] = av.x; As[colL + 1][rowL] = av.y;
        As[colL + 2][rowL] = av.z; As[colL + 3][rowL] = av.w;
        Ws[colL + 0][rowL] = wv.x; Ws[colL + 1][rowL] = wv.y;
        Ws[colL + 2][rowL] = wv.z; Ws[colL + 3][rowL] = wv.w;
        __syncthreads();
        if (k0 + 8 < K) {
            av = *(const float4*)(Ag + k0 + 8);
            wv = *(const float4*)(Wg + k0 + 8);
        }
#pragma unroll
        for (int k = 0; k < 8; ++k) {
            float a[8], b[8];
#pragma unroll
            for (int i = 0; i < 8; ++i) a[i] = As[k][ty * 8 + i];
#pragma unroll
            for (int j = 0; j < 8; ++j) b[j] = Ws[k][tx * 8 + j];
#pragma unroll
            for (int i = 0; i < 8; ++i)
#pragma unroll
                for (int j = 0; j < 8; ++j)
                    acc[i][j] += a[i] * b[j];
        }
    }

    float bn[8];
#pragma unroll
    for (int j = 0; j < 8; ++j) bn[j] = bias[n0 + tx * 8 + j];

    float* Cp = C + (size_t)(m0 + ty * 8) * HIDDEN + n0 + tx * 8;
#pragma unroll
    for (int i = 0; i < 8; ++i) {
        float4 v0, v1;
        v0.x = acc[i][0] + bn[0]; v0.y = acc[i][1] + bn[1];
        v0.z = acc[i][2] + bn[2]; v0.w = acc[i][3] + bn[3];
        v1.x = acc[i][4] + bn[4]; v1.y = acc[i][5] + bn[5];
        v1.z = acc[i][6] + bn[6]; v1.w = acc[i][7] + bn[7];
        *(float4*)(Cp + (size_t)i * HIDDEN)     = v0;
        *(float4*)(Cp + (size_t)i * HIDDEN + 4) = v1;
    }
}

// ---------------------------------------------------------------------------
// Persistent recurrence, cluster + DSMEM mbarrier version.
//   cluster = 8 CTAs = one batch group (4 batches); CTA r owns cols [64r,64r+64).
//   Per step: local stage -> block push (v4) to 7 peers -> remote mbarrier
//   arrives (release.cluster) -> local acquire wait.
// ---------------------------------------------------------------------------
__global__ __launch_bounds__(RT, 1) __cluster_dims__(CBLKS, 1, 1)
void rnn_rec(
    const float* __restrict__ P,
    const float* __restrict__ Wfull, int ldw, int koff,
    const float* __restrict__ h0,
    float* __restrict__ states,
    float* __restrict__ last)
{
    extern __shared__ float sh[];
    float* Whs = sh;                         // [64][WPAD]
    float* Hsb = sh + CPB * WPAD;            // [2][BG][HPAD]
    unsigned long long* mbar =
        (unsigned long long*)(sh + CPB * WPAD + 2 * BG * HPAD);

    const int tid  = threadIdx.x;
    const int cblk = blockIdx.x & (CBLKS - 1);   // cluster rank
    const int grp  = blockIdx.x >> 3;
    const int j0   = cblk * CPB;
    const int bl   = tid & (BG - 1);         // 0..3 local batch
    const int jl   = tid >> 2;               // 0..63 local column
    const int j    = j0 + jl;
    const int b    = grp * BG + bl;

    // Load this CTA's Wh rows (64 x 512) into padded smem.
    for (int idx = tid; idx < CPB * HIDDEN; idx += RT) {
        int r = idx >> 9, k = idx & 511;
        Whs[r * WPAD + k] = Wfull[(size_t)(j0 + r) * ldw + koff + k];
    }
    // Stage h0 for our 4 batches into buffer 0 (full 512-vector per batch).
    for (int i = tid; i < BG * HIDDEN; i += RT) {
        int bb = i >> 9, k = i & 511;
        Hsb[bb * HPAD + k] = h0[(size_t)(grp * BG + bb) * HIDDEN + k];
    }
    if (tid == 0) {
        asm volatile("mbarrier.init.shared.b64 [%0], %1;"
                     :: "r"(smem_u32(mbar)), "r"(CBLKS) : "memory");
    }
    __syncthreads();
    // All mbarriers initialized cluster-wide before any remote arrive.
    asm volatile("barrier.cluster.arrive.aligned;" ::: "memory");
    asm volatile("barrier.cluster.wait.aligned;"   ::: "memory");

    const longlong2* w2 = (const longlong2*)(Whs + jl * WPAD);
    const unsigned mbar_loc = smem_u32(mbar);

    float p = P[((size_t)0 * BATCH + b) * HIDDEN + j];

    for (int t = 0; t < T_STEPS; ++t) {
        const int cur = t & 1, nxt = cur ^ 1;

        const longlong2* h2 = (const longlong2*)(Hsb + (cur * BG + bl) * HPAD);
        long long a0 = 0, a1 = 0, a2 = 0, a3 = 0;
#pragma unroll 16
        for (int i = 0; i < HIDDEN / 4; ++i) {       // 128 x (float4 . float4)
            longlong2 w = w2[i];
            longlong2 h = h2[i];
            if (i & 1) { FMA2(a2, w.x, h.x); FMA2(a3, w.y, h.y); }
            else       { FMA2(a0, w.x, h.x); FMA2(a1, w.y, h.y); }
        }
        float2 f0 = *reinterpret_cast<float2*>(&a0);
        float2 f1 = *reinterpret_cast<float2*>(&a1);
        float2 f2 = *reinterpret_cast<float2*>(&a2);
        float2 f3 = *reinterpret_cast<float2*>(&a3);
        float acc = ((f0.x + f0.y) + (f1.x + f1.y)) +
                    ((f2.x + f2.y) + (f3.x + f3.y));
        float hv = tanhf(p + acc);

        states[((size_t)t * BATCH + b) * HIDDEN + j] = hv;

        if (t == T_STEPS - 1) {
            last[(size_t)b * HIDDEN + j] = hv;
            break;                                   // no exchange needed
        }

        // Stage locally (our 64-col block of the next h buffer).
        Hsb[(nxt * BG + bl) * HPAD + j] = hv;
        __syncthreads();

        // Push our 1KB block (64 float4) to the 7 peer CTAs.
        for (int pidx = tid; pidx < 7 * 64; pidx += RT) {
            int rr   = pidx >> 6;                    // 0..6
            int e    = pidx & 63;
            int row  = e >> 4, c = e & 15;
            int off  = (nxt * BG + row) * HPAD + j0 + c * 4;
            float4 v = *(const float4*)(Hsb + off);
            unsigned loc = smem_u32(Hsb + off);
            unsigned dst;
            int rank = (cblk + 1 + rr) & (CBLKS - 1);
            asm("mapa.shared::cluster.u32 %0, %1, %2;"
                : "=r"(dst) : "r"(loc), "r"(rank));
            asm volatile("st.shared::cluster.v4.f32 [%0], {%1,%2,%3,%4};"
                         :: "r"(dst), "f"(v.x), "f"(v.y), "f"(v.z), "f"(v.w)
                         : "memory");
        }
        __syncthreads();

        // Threads 0..7: release-arrive on every cluster CTA's mbarrier.
        if (tid < CBLKS) {
            asm volatile("fence.acq_rel.cluster;" ::: "memory");
            unsigned remote;
            asm("mapa.shared::cluster.u32 %0, %1, %2;"
                : "=r"(remote) : "r"(mbar_loc), "r"(tid));
            asm volatile("mbarrier.arrive.release.cluster.shared::cluster.b64 _, [%0];"
                         :: "r"(remote) : "memory");
        }

        // Prefetch next step's P while the group syncs.
        p = P[((size_t)(t + 1) * BATCH + b) * HIDDEN + j];

        // Wait for all 8 arrivals (phase parity = t&1), acquire at cluster scope.
        {
            unsigned parity = (unsigned)(t & 1);
            asm volatile(
                "{\n\t"
                ".reg .pred Pq;\n\t"
                "WAIT_%=:\n\t"
                "mbarrier.try_wait.parity.acquire.cluster.shared::cta.b64 Pq, [%0], %1;\n\t"
                "@!Pq bra WAIT_%=;\n\t"
                "}"
                :: "r"(mbar_loc), "r"(parity) : "memory");
        }
    }

    // No CTA may exit while peers could still push into its smem.
    asm volatile("barrier.cluster.arrive.aligned;" ::: "memory");
    asm volatile("barrier.cluster.wait.aligned;"   ::: "memory");
}

// ---------------------------------------------------------------------------
extern "C" void kernel_launch(void* const* d_in, const int* in_sizes, int n_in,
                              void* d_out, int out_size)
{
    (void)in_sizes; (void)n_in; (void)out_size;
    const float* inputs = (const float*)d_in[0];
    const float* H      = (const float*)d_in[1];
    const float* W_net  = (const float*)d_in[2];
    const float* b_net  = (const float*)d_in[3];
    const float* W_deep = (const float*)d_in[4];
    const float* b_deep = (const float*)d_in[5];

    float* out     = (float*)d_out;
    float* states1 = out;
    float* lasts   = out + (size_t)T_STEPS * BATCH * HIDDEN;

    float *P, *S0;
    cudaGetSymbolAddress((void**)&P,  g_P);
    cudaGetSymbolAddress((void**)&S0, g_S0);

    cudaFuncSetAttribute(rnn_rec, cudaFuncAttributeMaxDynamicSharedMemorySize, REC_SMEM);

    dim3 ggrid(HIDDEN / 128, (T_STEPS * BATCH) / 128);

    gemm_awt<<<ggrid, 256>>>(inputs, W_net, b_net, P, VDIM, VDIM + HIDDEN);
    rnn_rec<<<NB, RT, REC_SMEM>>>(P, W_net, VDIM + HIDDEN, VDIM, H, S0, lasts);

    gemm_awt<<<ggrid, 256>>>(S0, W_deep, b_deep, P, HIDDEN, 2 * HIDDEN);
    rnn_rec<<<NB, RT, REC_SMEM>>>(P, W_deep, 2 * HIDDEN, HIDDEN,
                                  H + BATCH * HIDDEN, states1,
                                  lasts + BATCH * HIDDEN);
}

// round 7
// speedup vs baseline: 1.0465x; 1.0465x over previous
#include <cuda_runtime.h>
#include <math.h>
#include <stdint.h>

#define T_STEPS 1024
#define BATCH   64
#define VDIM    256
#define HIDDEN  512
#define CPB     64                 // columns per CTA
#define BG      4                  // batches per group
#define CBLKS   (HIDDEN / CPB)     // 8 CTAs per group
#define GROUPS  (BATCH / BG)       // 16 groups
#define NB      (CBLKS * GROUPS)   // 128 CTAs
#define RT      512                // 64 cols x 8 k-chunks
#define HPAD    544                // per-batch h smem stride (floats), swizzled
#define REC_SMEM (120 * 1024)      // oversized: forces 1 CTA/SM

// Scratch (device globals: allocation APIs are forbidden)
__device__ float g_P [(size_t)T_STEPS * BATCH * HIDDEN];
__device__ float g_S0[(size_t)T_STEPS * BATCH * HIDDEN];
__device__ float g_Hbuf[2][GROUPS][BG * HIDDEN];

struct PadU { unsigned v; unsigned pad[63]; };
__device__ PadU g_count[GROUPS];
__device__ PadU g_gen[GROUPS];

#define FMA2(acc, w, h) \
    asm("fma.rn.f32x2 %0, %1, %2, %0;" : "+l"(acc) : "l"(w), "l"(h))

__device__ __forceinline__ unsigned smem_u32(const void* p) {
    return (unsigned)__cvta_generic_to_shared(p);
}
__device__ __forceinline__ void cp16(unsigned s, const void* g) {
    asm volatile("cp.async.cg.shared.global [%0], [%1], 16;" :: "r"(s), "l"(g));
}

// ---------------------------------------------------------------------------
// GEMM: C[m][n] = sum_k A[m][k]*W[n*ldw+k] + bias[n], C row stride = HIDDEN
// ---------------------------------------------------------------------------
__global__ __launch_bounds__(256) void gemm_awt(
    const float* __restrict__ A, const float* __restrict__ W,
    const float* __restrict__ bias, float* __restrict__ C,
    int K, int ldw)
{
    __shared__ float As[8][128];
    __shared__ float Ws[8][128];

    const int tid = threadIdx.x;
    const int m0 = blockIdx.y * 128;
    const int n0 = blockIdx.x * 128;
    const int tx = tid & 15;
    const int ty = tid >> 4;
    const int rowL = tid >> 1;
    const int colL = (tid & 1) * 4;

    const float* Ag = A + (size_t)(m0 + rowL) * K + colL;
    const float* Wg = W + (size_t)(n0 + rowL) * ldw + colL;

    float acc[8][8];
#pragma unroll
    for (int i = 0; i < 8; ++i)
#pragma unroll
        for (int j = 0; j < 8; ++j) acc[i][j] = 0.f;

    float4 av = *(const float4*)(Ag);
    float4 wv = *(const float4*)(Wg);

    for (int k0 = 0; k0 < K; k0 += 8) {
        __syncthreads();
        As[colL + 0][rowL] = av.x; As[colL + 1][rowL] = av.y;
        As[colL + 2][rowL] = av.z; As[colL + 3][rowL] = av.w;
        Ws[colL + 0][rowL] = wv.x; Ws[colL + 1][rowL] = wv.y;
        Ws[colL + 2][rowL] = wv.z; Ws[colL + 3][rowL] = wv.w;
        __syncthreads();
        if (k0 + 8 < K) {
            av = *(const float4*)(Ag + k0 + 8);
            wv = *(const float4*)(Wg + k0 + 8);
        }
#pragma unroll
        for (int k = 0; k < 8; ++k) {
            float a[8], b[8];
#pragma unroll
            for (int i = 0; i < 8; ++i) a[i] = As[k][ty * 8 + i];
#pragma unroll
            for (int j = 0; j < 8; ++j) b[j] = Ws[k][tx * 8 + j];
#pragma unroll
            for (int i = 0; i < 8; ++i)
#pragma unroll
                for (int j = 0; j < 8; ++j)
                    acc[i][j] += a[i] * b[j];
        }
    }

    float bn[8];
#pragma unroll
    for (int j = 0; j < 8; ++j) bn[j] = bias[n0 + tx * 8 + j];

    float* Cp = C + (size_t)(m0 + ty * 8) * HIDDEN + n0 + tx * 8;
#pragma unroll
    for (int i = 0; i < 8; ++i) {
        float4 v0, v1;
        v0.x = acc[i][0] + bn[0]; v0.y = acc[i][1] + bn[1];
        v0.z = acc[i][2] + bn[2]; v0.w = acc[i][3] + bn[3];
        v1.x = acc[i][4] + bn[4]; v1.y = acc[i][5] + bn[5];
        v1.z = acc[i][6] + bn[6]; v1.w = acc[i][7] + bn[7];
        *(float4*)(Cp + (size_t)i * HIDDEN)     = v0;
        *(float4*)(Cp + (size_t)i * HIDDEN + 4) = v1;
    }
}

// ---------------------------------------------------------------------------
// Persistent recurrence, register-weight version.
//   512 threads: jl = tid>>3 (column), kc = tid&7 (64-wide k-chunk).
//   Thread keeps its 64 Wh weights in registers for the entire scan.
//   Per step: 4 partial dots (one per batch) -> shfl reduce over kc ->
//   tanh -> publish to L2 -> group barrier -> restage h (8 KB) to smem.
// ---------------------------------------------------------------------------
__global__ __launch_bounds__(RT, 1) void rnn_rec(
    const float* __restrict__ P,
    const float* __restrict__ Wfull, int ldw, int koff,
    const float* __restrict__ h0,
    float* __restrict__ states,
    float* __restrict__ last)
{
    extern __shared__ float sh[];
    float* Hs = sh;                            // [BG][HPAD], swizzled

    const int tid  = threadIdx.x;
    const int cblk = blockIdx.x & (CBLKS - 1);
    const int grp  = blockIdx.x >> 3;
    const int j0   = cblk * CPB;
    const int jl   = tid >> 3;                 // 0..63
    const int kc   = tid & 7;                  // 0..7
    const int j    = j0 + jl;
    const int bq   = grp * BG + (kc & 3);      // output batch for kc<4 lanes

    // Load this thread's 64 Wh weights into registers (fixed for all steps).
    union LLF { float4 f; longlong2 l; };
    longlong2 wr[16];
    {
        const float* wp = Wfull + (size_t)j * ldw + koff + kc * 64;
#pragma unroll
        for (int i = 0; i < 16; ++i) {
            LLF u; u.f = *(const float4*)(wp + i * 4);
            wr[i] = u.l;
        }
    }

    // Stage h0: Hs[bb][k + (k>>6)*4] = h0[(grp*4+bb)*512 + k]
    for (int i = tid; i < BG * HIDDEN; i += RT) {
        int bb = i >> 9, k = i & 511;
        Hs[bb * HPAD + k + ((k >> 6) << 2)] =
            h0[(size_t)(grp * BG + bb) * HIDDEN + k];
    }
    __syncthreads();

    unsigned gen = *(volatile unsigned*)&g_gen[grp].v;

    for (int t = 0; t < T_STEPS; ++t) {
        float p = P[((size_t)t * BATCH + bq) * HIDDEN + j];  // early LDG

        // 4 partial dots over our 64-wide chunk (phys offset kc*68, 16B aligned).
        long long a0 = 0, a1 = 0, a2 = 0, a3 = 0;
        const longlong2* hp0 = (const longlong2*)(Hs + 0 * HPAD + kc * 68);
        const longlong2* hp1 = (const longlong2*)(Hs + 1 * HPAD + kc * 68);
        const longlong2* hp2 = (const longlong2*)(Hs + 2 * HPAD + kc * 68);
        const longlong2* hp3 = (const longlong2*)(Hs + 3 * HPAD + kc * 68);
#pragma unroll
        for (int i = 0; i < 16; ++i) {
            longlong2 w = wr[i];
            longlong2 h0v = hp0[i]; FMA2(a0, w.x, h0v.x); FMA2(a0, w.y, h0v.y);
            longlong2 h1v = hp1[i]; FMA2(a1, w.x, h1v.x); FMA2(a1, w.y, h1v.y);
            longlong2 h2v = hp2[i]; FMA2(a2, w.x, h2v.x); FMA2(a2, w.y, h2v.y);
            longlong2 h3v = hp3[i]; FMA2(a3, w.x, h3v.x); FMA2(a3, w.y, h3v.y);
        }
        float2 f0 = *reinterpret_cast<float2*>(&a0);
        float2 f1 = *reinterpret_cast<float2*>(&a1);
        float2 f2 = *reinterpret_cast<float2*>(&a2);
        float2 f3 = *reinterpret_cast<float2*>(&a3);
        float s0 = f0.x + f0.y, s1 = f1.x + f1.y;
        float s2 = f2.x + f2.y, s3 = f3.x + f3.y;

        // Reduce across the 8 kc lanes (lanes 8m..8m+7 share jl).
#pragma unroll
        for (int m = 1; m < 8; m <<= 1) {
            s0 += __shfl_xor_sync(0xffffffffu, s0, m);
            s1 += __shfl_xor_sync(0xffffffffu, s1, m);
            s2 += __shfl_xor_sync(0xffffffffu, s2, m);
            s3 += __shfl_xor_sync(0xffffffffu, s3, m);
        }
        float r  = (kc == 0) ? s0 : (kc == 1) ? s1 : (kc == 2) ? s2 : s3;
        float hv = tanhf(p + r);

        if (kc < 4) {
            states[((size_t)t * BATCH + bq) * HIDDEN + j] = hv;
            if (t == T_STEPS - 1) last[(size_t)bq * HIDDEN + j] = hv;
            else g_Hbuf[t & 1][grp][(kc & 3) * HIDDEN + j] = hv;
        }
        if (t == T_STEPS - 1) break;

        // ---- group barrier (8 CTAs): atomic arrive, plain-load poll ----
        __threadfence();
        __syncthreads();
        if (tid == 0) {
            unsigned tk = atomicAdd(&g_count[grp].v, 1u);
            if (tk == CBLKS - 1u) {
                *(volatile unsigned*)&g_count[grp].v = 0u;
                __threadfence();
                *(volatile unsigned*)&g_gen[grp].v = gen + 1u;
            } else {
                while (*(volatile unsigned*)&g_gen[grp].v == gen) { }
            }
            __threadfence();
        }
        __syncthreads();
        ++gen;

        // ---- restage h (8 KB): one cp.async.cg 16B per thread ----
        {
            int bb = tid >> 7, k0 = (tid & 127) << 2;
            const float* src = &g_Hbuf[t & 1][grp][bb * HIDDEN + k0];
            cp16(smem_u32(Hs + bb * HPAD + k0 + ((k0 >> 6) << 2)), src);
            asm volatile("cp.async.commit_group;");
            asm volatile("cp.async.wait_group 0;");
        }
        __syncthreads();
    }
}

// ---------------------------------------------------------------------------
extern "C" void kernel_launch(void* const* d_in, const int* in_sizes, int n_in,
                              void* d_out, int out_size)
{
    (void)in_sizes; (void)n_in; (void)out_size;
    const float* inputs = (const float*)d_in[0];
    const float* H      = (const float*)d_in[1];
    const float* W_net  = (const float*)d_in[2];
    const float* b_net  = (const float*)d_in[3];
    const float* W_deep = (const float*)d_in[4];
    const float* b_deep = (const float*)d_in[5];

    float* out     = (float*)d_out;
    float* states1 = out;
    float* lasts   = out + (size_t)T_STEPS * BATCH * HIDDEN;

    float *P, *S0;
    cudaGetSymbolAddress((void**)&P,  g_P);
    cudaGetSymbolAddress((void**)&S0, g_S0);

    cudaFuncSetAttribute(rnn_rec, cudaFuncAttributeMaxDynamicSharedMemorySize, REC_SMEM);

    dim3 ggrid(HIDDEN / 128, (T_STEPS * BATCH) / 128);

    gemm_awt<<<ggrid, 256>>>(inputs, W_net, b_net, P, VDIM, VDIM + HIDDEN);
    rnn_rec<<<NB, RT, REC_SMEM>>>(P, W_net, VDIM + HIDDEN, VDIM, H, S0, lasts);

    gemm_awt<<<ggrid, 256>>>(S0, W_deep, b_deep, P, HIDDEN, 2 * HIDDEN);
    rnn_rec<<<NB, RT, REC_SMEM>>>(P, W_deep, 2 * HIDDEN, HIDDEN,
                                  H + BATCH * HIDDEN, states1,
                                  lasts + BATCH * HIDDEN);
}

// round 8
// speedup vs baseline: 1.4797x; 1.4140x over previous
#include <cuda_runtime.h>
#include <math.h>
#include <stdint.h>

#define T_STEPS 1024
#define BATCH   64
#define VDIM    256
#define HIDDEN  512
#define CPB     64                 // columns per CTA
#define BG      4                  // batches per group
#define CBLKS   (HIDDEN / CPB)     // 8 CTAs per group
#define GROUPS  (BATCH / BG)       // 16 groups
#define NB      (CBLKS * GROUPS)   // 128 CTAs
#define RT      256
#define CHPAD   36                 // padded k-chunk stride (32 data + 4 pad)
#define BHSTR   (16 * CHPAD)       // per-batch h stride = 576 floats
#define PSTR    21                 // partial row stride (16 data + 5 pad)
#define REC_SMEM (120 * 1024)      // oversized: forces 1 CTA/SM

// Scratch (device globals: allocation APIs are forbidden)
__device__ float g_P [(size_t)T_STEPS * BATCH * HIDDEN];
__device__ float g_S0[(size_t)T_STEPS * BATCH * HIDDEN];
__device__ float g_Hbuf[2][GROUPS][BG * HIDDEN];

struct PadU { unsigned v; unsigned pad[63]; };
__device__ PadU g_count[GROUPS];
__device__ PadU g_gen[GROUPS];

#define FMA2(acc, w, h) \
    asm("fma.rn.f32x2 %0, %1, %2, %0;" : "+l"(acc) : "l"(w), "l"(h))

__device__ __forceinline__ unsigned smem_u32(const void* p) {
    return (unsigned)__cvta_generic_to_shared(p);
}
__device__ __forceinline__ void cp16(unsigned s, const void* g) {
    asm volatile("cp.async.cg.shared.global [%0], [%1], 16;" :: "r"(s), "l"(g));
}

// ---------------------------------------------------------------------------
// GEMM: C[m][n] = sum_k A[m][k]*W[n*ldw+k] + bias[n], C row stride = HIDDEN
// ---------------------------------------------------------------------------
__global__ __launch_bounds__(256) void gemm_awt(
    const float* __restrict__ A, const float* __restrict__ W,
    const float* __restrict__ bias, float* __restrict__ C,
    int K, int ldw)
{
    __shared__ float As[8][128];
    __shared__ float Ws[8][128];

    const int tid = threadIdx.x;
    const int m0 = blockIdx.y * 128;
    const int n0 = blockIdx.x * 128;
    const int tx = tid & 15;
    const int ty = tid >> 4;
    const int rowL = tid >> 1;
    const int colL = (tid & 1) * 4;

    const float* Ag = A + (size_t)(m0 + rowL) * K + colL;
    const float* Wg = W + (size_t)(n0 + rowL) * ldw + colL;

    float acc[8][8];
#pragma unroll
    for (int i = 0; i < 8; ++i)
#pragma unroll
        for (int j = 0; j < 8; ++j) acc[i][j] = 0.f;

    float4 av = *(const float4*)(Ag);
    float4 wv = *(const float4*)(Wg);

    for (int k0 = 0; k0 < K; k0 += 8) {
        __syncthreads();
        As[colL + 0][rowL] = av.x; As[colL + 1][rowL] = av.y;
        As[colL + 2][rowL] = av.z; As[colL + 3][rowL] = av.w;
        Ws[colL + 0][rowL] = wv.x; Ws[colL + 1][rowL] = wv.y;
        Ws[colL + 2][rowL] = wv.z; Ws[colL + 3][rowL] = wv.w;
        __syncthreads();
        if (k0 + 8 < K) {
            av = *(const float4*)(Ag + k0 + 8);
            wv = *(const float4*)(Wg + k0 + 8);
        }
#pragma unroll
        for (int k = 0; k < 8; ++k) {
            float a[8], b[8];
#pragma unroll
            for (int i = 0; i < 8; ++i) a[i] = As[k][ty * 8 + i];
#pragma unroll
            for (int j = 0; j < 8; ++j) b[j] = Ws[k][tx * 8 + j];
#pragma unroll
            for (int i = 0; i < 8; ++i)
#pragma unroll
                for (int j = 0; j < 8; ++j)
                    acc[i][j] += a[i] * b[j];
        }
    }

    float bn[8];
#pragma unroll
    for (int j = 0; j < 8; ++j) bn[j] = bias[n0 + tx * 8 + j];

    float* Cp = C + (size_t)(m0 + ty * 8) * HIDDEN + n0 + tx * 8;
#pragma unroll
    for (int i = 0; i < 8; ++i) {
        float4 v0, v1;
        v0.x = acc[i][0] + bn[0]; v0.y = acc[i][1] + bn[1];
        v0.z = acc[i][2] + bn[2]; v0.w = acc[i][3] + bn[3];
        v1.x = acc[i][4] + bn[4]; v1.y = acc[i][5] + bn[5];
        v1.z = acc[i][6] + bn[6]; v1.w = acc[i][7] + bn[7];
        *(float4*)(Cp + (size_t)i * HIDDEN)     = v0;
        *(float4*)(Cp + (size_t)i * HIDDEN + 4) = v1;
    }
}

// ---------------------------------------------------------------------------
// Persistent recurrence, register-blocked:
//   thread t: kc = t&15 (32-wide k-chunk), jg = t>>4 (4-col group).
//   Holds Wh[4 cols][32 k] in registers; computes 16 partials (4c x 4b)
//   per step (32 LDS.128 with 16-way broadcast dedup + 256 FMA2),
//   partial-reduce via padded smem; h exchange via L2; group barrier.
// ---------------------------------------------------------------------------
__global__ __launch_bounds__(RT, 1) void rnn_rec(
    const float* __restrict__ P,
    const float* __restrict__ Wfull, int ldw, int koff,
    const float* __restrict__ h0,
    float* __restrict__ states,
    float* __restrict__ last)
{
    extern __shared__ float sh[];
    float* Hs = sh;                       // [BG][BHSTR] chunk-padded h
    float* Ps = sh + BG * BHSTR;          // [256][PSTR] partials

    const int tid  = threadIdx.x;
    const int cblk = blockIdx.x & (CBLKS - 1);
    const int grp  = blockIdx.x >> 3;
    const int j0   = cblk * CPB;
    const int kc   = tid & 15;            // k-chunk index
    const int jg   = tid >> 4;            // 4-col group 0..15
    const int rb   = tid >> 6;            // reduce: batch 0..3
    const int rcol = tid & 63;            // reduce: local col
    const int rj   = j0 + rcol;
    const int rbg  = grp * BG + rb;       // reduce: global batch

    // Load Wh[4 cols][32 k] into registers (fixed for the whole scan).
    union LLF { float4 f; longlong2 l; };
    longlong2 wr[4][8];
#pragma unroll
    for (int c = 0; c < 4; ++c) {
        const float* wp = Wfull + (size_t)(j0 + jg * 4 + c) * ldw + koff + kc * 32;
#pragma unroll
        for (int i = 0; i < 8; ++i) {
            LLF u; u.f = *(const float4*)(wp + i * 4);
            wr[c][i] = u.l;
        }
    }

    // Stage h0: Hs[b][chunk-padded k].
    for (int i = tid; i < BG * HIDDEN; i += RT) {
        int b = i >> 9, k = i & 511;
        Hs[b * BHSTR + (k >> 5) * CHPAD + (k & 31)] =
            h0[(size_t)(grp * BG + b) * HIDDEN + k];
    }
    __syncthreads();

    unsigned gen = *(volatile unsigned*)&g_gen[grp].v;

    for (int t = 0; t < T_STEPS; ++t) {
        float p = P[((size_t)t * BATCH + rbg) * HIDDEN + rj];  // for reduce phase

        // ---- compute 16 partials over our 32-wide k-chunk ----
        long long acc[4][4];
#pragma unroll
        for (int c = 0; c < 4; ++c)
#pragma unroll
            for (int b = 0; b < 4; ++b) acc[c][b] = 0;

        const float* hc = Hs + kc * CHPAD;
#pragma unroll
        for (int i = 0; i < 8; ++i) {
            longlong2 hb[4];
#pragma unroll
            for (int b = 0; b < 4; ++b) {
                LLF u; u.f = *(const float4*)(hc + b * BHSTR + i * 4);
                hb[b] = u.l;
            }
#pragma unroll
            for (int c = 0; c < 4; ++c) {
                longlong2 w = wr[c][i];
#pragma unroll
                for (int b = 0; b < 4; ++b) {
                    FMA2(acc[c][b], w.x, hb[b].x);
                    FMA2(acc[c][b], w.y, hb[b].y);
                }
            }
        }
        // write partials: out o = b*64 + jg*4 + c
#pragma unroll
        for (int c = 0; c < 4; ++c)
#pragma unroll
            for (int b = 0; b < 4; ++b) {
                float2 f = *reinterpret_cast<float2*>(&acc[c][b]);
                Ps[(b * 64 + jg * 4 + c) * PSTR + kc] = f.x + f.y;
            }
        __syncthreads();

        // ---- reduce: thread tid owns output (rb, rcol) ----
        float s = 0.f;
        const float* pr = Ps + tid * PSTR;
#pragma unroll
        for (int i = 0; i < 16; ++i) s += pr[i];
        float hv = tanhf(p + s);

        states[((size_t)t * BATCH + rbg) * HIDDEN + rj] = hv;
        if (t == T_STEPS - 1) {
            last[(size_t)rbg * HIDDEN + rj] = hv;
            break;
        }
        g_Hbuf[t & 1][grp][rb * HIDDEN + rj] = hv;

        // ---- group barrier (8 CTAs) ----
        __threadfence();
        __syncthreads();
        if (tid == 0) {
            unsigned tk = atomicAdd(&g_count[grp].v, 1u);
            if (tk == CBLKS - 1u) {
                *(volatile unsigned*)&g_count[grp].v = 0u;
                __threadfence();
                *(volatile unsigned*)&g_gen[grp].v = gen + 1u;
            } else {
                while (*(volatile unsigned*)&g_gen[grp].v == gen) { }
            }
            __threadfence();
        }
        __syncthreads();
        ++gen;

        // ---- restage h (8 KB) into chunk-padded smem ----
        const float* src = &g_Hbuf[t & 1][grp][0];
#pragma unroll
        for (int u = 0; u < 2; ++u) {
            int idx = tid + u * RT;            // float4 index 0..511
            int b = idx >> 7, k = (idx & 127) << 2;
            float* dst = Hs + b * BHSTR + (k >> 5) * CHPAD + (k & 31);
            cp16(smem_u32(dst), src + b * HIDDEN + k);
        }
        asm volatile("cp.async.commit_group;");
        asm volatile("cp.async.wait_group 0;");
        __syncthreads();
    }
}

// ---------------------------------------------------------------------------
extern "C" void kernel_launch(void* const* d_in, const int* in_sizes, int n_in,
                              void* d_out, int out_size)
{
    (void)in_sizes; (void)n_in; (void)out_size;
    const float* inputs = (const float*)d_in[0];
    const float* H      = (const float*)d_in[1];
    const float* W_net  = (const float*)d_in[2];
    const float* b_net  = (const float*)d_in[3];
    const float* W_deep = (const float*)d_in[4];
    const float* b_deep = (const float*)d_in[5];

    float* out     = (float*)d_out;
    float* states1 = out;
    float* lasts   = out + (size_t)T_STEPS * BATCH * HIDDEN;

    float *P, *S0;
    cudaGetSymbolAddress((void**)&P,  g_P);
    cudaGetSymbolAddress((void**)&S0, g_S0);

    cudaFuncSetAttribute(rnn_rec, cudaFuncAttributeMaxDynamicSharedMemorySize, REC_SMEM);

    dim3 ggrid(HIDDEN / 128, (T_STEPS * BATCH) / 128);

    gemm_awt<<<ggrid, 256>>>(inputs, W_net, b_net, P, VDIM, VDIM + HIDDEN);
    rnn_rec<<<NB, RT, REC_SMEM>>>(P, W_net, VDIM + HIDDEN, VDIM, H, S0, lasts);

    gemm_awt<<<ggrid, 256>>>(S0, W_deep, b_deep, P, HIDDEN, 2 * HIDDEN);
    rnn_rec<<<NB, RT, REC_SMEM>>>(P, W_deep, 2 * HIDDEN, HIDDEN,
                                  H + BATCH * HIDDEN, states1,
                                  lasts + BATCH * HIDDEN);
}

// round 9
// speedup vs baseline: 2.0939x; 1.4150x over previous
#include <cuda_runtime.h>
#include <math.h>
#include <stdint.h>

#define T_STEPS 1024
#define BATCH   64
#define VDIM    256
#define HIDDEN  512
#define CPB     64                 // columns per CTA
#define BG      4                  // batches per group
#define CBLKS   (HIDDEN / CPB)     // 8 CTAs per group
#define GROUPS  (BATCH / BG)       // 16 groups
#define NB      (CBLKS * GROUPS)   // 128 CTAs
#define RT      256
#define CHPAD   36                 // padded k-chunk stride (32 data + 4 pad)
#define BHSTR   (16 * CHPAD)       // per-batch h stride = 576 floats
#define PSTR    21                 // partial row stride (16 data + 5 pad)
#define REC_SMEM (120 * 1024)      // oversized: forces 1 CTA/SM

// Scratch (device globals: allocation APIs are forbidden)
__device__ float g_P [(size_t)T_STEPS * BATCH * HIDDEN];
__device__ float g_S0[(size_t)T_STEPS * BATCH * HIDDEN];
__device__ float g_Hbuf[2][GROUPS][BG * HIDDEN];

struct PadU { unsigned v; unsigned pad[63]; };
__device__ PadU g_count[GROUPS];
__device__ PadU g_gen[GROUPS];

#define FMA2(acc, w, h) \
    asm("fma.rn.f32x2 %0, %1, %2, %0;" : "+l"(acc) : "l"(w), "l"(h))

__device__ __forceinline__ unsigned smem_u32(const void* p) {
    return (unsigned)__cvta_generic_to_shared(p);
}
__device__ __forceinline__ void cp16(unsigned s, const void* g) {
    asm volatile("cp.async.cg.shared.global [%0], [%1], 16;" :: "r"(s), "l"(g));
}

// ---------------------------------------------------------------------------
// GEMM: C[m][n] = sum_k A[m][k]*W[n*ldw+k] + bias[n], C row stride = HIDDEN
// ---------------------------------------------------------------------------
__global__ __launch_bounds__(256) void gemm_awt(
    const float* __restrict__ A, const float* __restrict__ W,
    const float* __restrict__ bias, float* __restrict__ C,
    int K, int ldw)
{
    __shared__ float As[8][128];
    __shared__ float Ws[8][128];

    const int tid = threadIdx.x;
    const int m0 = blockIdx.y * 128;
    const int n0 = blockIdx.x * 128;
    const int tx = tid & 15;
    const int ty = tid >> 4;
    const int rowL = tid >> 1;
    const int colL = (tid & 1) * 4;

    const float* Ag = A + (size_t)(m0 + rowL) * K + colL;
    const float* Wg = W + (size_t)(n0 + rowL) * ldw + colL;

    float acc[8][8];
#pragma unroll
    for (int i = 0; i < 8; ++i)
#pragma unroll
        for (int j = 0; j < 8; ++j) acc[i][j] = 0.f;

    float4 av = *(const float4*)(Ag);
    float4 wv = *(const float4*)(Wg);

    for (int k0 = 0; k0 < K; k0 += 8) {
        __syncthreads();
        As[colL + 0][rowL] = av.x; As[colL + 1][rowL] = av.y;
        As[colL + 2][rowL] = av.z; As[colL + 3][rowL] = av.w;
        Ws[colL + 0][rowL] = wv.x; Ws[colL + 1][rowL] = wv.y;
        Ws[colL + 2][rowL] = wv.z; Ws[colL + 3][rowL] = wv.w;
        __syncthreads();
        if (k0 + 8 < K) {
            av = *(const float4*)(Ag + k0 + 8);
            wv = *(const float4*)(Wg + k0 + 8);
        }
#pragma unroll
        for (int k = 0; k < 8; ++k) {
            float a[8], b[8];
#pragma unroll
            for (int i = 0; i < 8; ++i) a[i] = As[k][ty * 8 + i];
#pragma unroll
            for (int j = 0; j < 8; ++j) b[j] = Ws[k][tx * 8 + j];
#pragma unroll
            for (int i = 0; i < 8; ++i)
#pragma unroll
                for (int j = 0; j < 8; ++j)
                    acc[i][j] += a[i] * b[j];
        }
    }

    float bn[8];
#pragma unroll
    for (int j = 0; j < 8; ++j) bn[j] = bias[n0 + tx * 8 + j];

    float* Cp = C + (size_t)(m0 + ty * 8) * HIDDEN + n0 + tx * 8;
#pragma unroll
    for (int i = 0; i < 8; ++i) {
        float4 v0, v1;
        v0.x = acc[i][0] + bn[0]; v0.y = acc[i][1] + bn[1];
        v0.z = acc[i][2] + bn[2]; v0.w = acc[i][3] + bn[3];
        v1.x = acc[i][4] + bn[4]; v1.y = acc[i][5] + bn[5];
        v1.z = acc[i][6] + bn[6]; v1.w = acc[i][7] + bn[7];
        *(float4*)(Cp + (size_t)i * HIDDEN)     = v0;
        *(float4*)(Cp + (size_t)i * HIDDEN + 4) = v1;
    }
}

// ---------------------------------------------------------------------------
// Persistent recurrence, register-blocked:
//   thread t: kc = t&15 (32-wide k-chunk), jg = t>>4 (4-col group).
//   Holds Wh[4 cols][32 k] in registers; computes 16 partials (4c x 4b)
//   per step (32 LDS.128 with 16-way broadcast dedup + 256 FMA2),
//   partial-reduce via padded smem; h exchange via L2; group barrier.
// ---------------------------------------------------------------------------
__global__ __launch_bounds__(RT, 1) void rnn_rec(
    const float* __restrict__ P,
    const float* __restrict__ Wfull, int ldw, int koff,
    const float* __restrict__ h0,
    float* __restrict__ states,
    float* __restrict__ last)
{
    extern __shared__ float sh[];
    float* Hs = sh;                       // [BG][BHSTR] chunk-padded h
    float* Ps = sh + BG * BHSTR;          // [256][PSTR] partials

    const int tid  = threadIdx.x;
    const int cblk = blockIdx.x & (CBLKS - 1);
    const int grp  = blockIdx.x >> 3;
    const int j0   = cblk * CPB;
    const int kc   = tid & 15;            // k-chunk index
    const int jg   = tid >> 4;            // 4-col group 0..15
    const int rb   = tid >> 6;            // reduce: batch 0..3
    const int rcol = tid & 63;            // reduce: local col
    const int rj   = j0 + rcol;
    const int rbg  = grp * BG + rb;       // reduce: global batch

    // Load Wh[4 cols][32 k] into registers (fixed for the whole scan).
    union LLF { float4 f; longlong2 l; };
    longlong2 wr[4][8];
#pragma unroll
    for (int c = 0; c < 4; ++c) {
        const float* wp = Wfull + (size_t)(j0 + jg * 4 + c) * ldw + koff + kc * 32;
#pragma unroll
        for (int i = 0; i < 8; ++i) {
            LLF u; u.f = *(const float4*)(wp + i * 4);
            wr[c][i] = u.l;
        }
    }

    // Stage h0: Hs[b][chunk-padded k].
    for (int i = tid; i < BG * HIDDEN; i += RT) {
        int b = i >> 9, k = i & 511;
        Hs[b * BHSTR + (k >> 5) * CHPAD + (k & 31)] =
            h0[(size_t)(grp * BG + b) * HIDDEN + k];
    }
    __syncthreads();

    unsigned gen = *(volatile unsigned*)&g_gen[grp].v;

    for (int t = 0; t < T_STEPS; ++t) {
        float p = P[((size_t)t * BATCH + rbg) * HIDDEN + rj];  // for reduce phase

        // ---- compute 16 partials over our 32-wide k-chunk ----
        long long acc[4][4];
#pragma unroll
        for (int c = 0; c < 4; ++c)
#pragma unroll
            for (int b = 0; b < 4; ++b) acc[c][b] = 0;

        const float* hc = Hs + kc * CHPAD;
#pragma unroll
        for (int i = 0; i < 8; ++i) {
            longlong2 hb[4];
#pragma unroll
            for (int b = 0; b < 4; ++b) {
                LLF u; u.f = *(const float4*)(hc + b * BHSTR + i * 4);
                hb[b] = u.l;
            }
#pragma unroll
            for (int c = 0; c < 4; ++c) {
                longlong2 w = wr[c][i];
#pragma unroll
                for (int b = 0; b < 4; ++b) {
                    FMA2(acc[c][b], w.x, hb[b].x);
                    FMA2(acc[c][b], w.y, hb[b].y);
                }
            }
        }
        // write partials: out o = b*64 + jg*4 + c
#pragma unroll
        for (int c = 0; c < 4; ++c)
#pragma unroll
            for (int b = 0; b < 4; ++b) {
                float2 f = *reinterpret_cast<float2*>(&acc[c][b]);
                Ps[(b * 64 + jg * 4 + c) * PSTR + kc] = f.x + f.y;
            }
        __syncthreads();

        // ---- reduce: thread tid owns output (rb, rcol) ----
        float s = 0.f;
        const float* pr = Ps + tid * PSTR;
#pragma unroll
        for (int i = 0; i < 16; ++i) s += pr[i];
        float hv = tanhf(p + s);

        states[((size_t)t * BATCH + rbg) * HIDDEN + rj] = hv;
        if (t == T_STEPS - 1) {
            last[(size_t)rbg * HIDDEN + rj] = hv;
            break;
        }
        g_Hbuf[t & 1][grp][rb * HIDDEN + rj] = hv;

        // ---- group barrier (8 CTAs) ----
        __threadfence();
        __syncthreads();
        if (tid == 0) {
            unsigned tk = atomicAdd(&g_count[grp].v, 1u);
            if (tk == CBLKS - 1u) {
                *(volatile unsigned*)&g_count[grp].v = 0u;
                __threadfence();
                *(volatile unsigned*)&g_gen[grp].v = gen + 1u;
            } else {
                while (*(volatile unsigned*)&g_gen[grp].v == gen) { }
            }
            __threadfence();
        }
        __syncthreads();
        ++gen;

        // ---- restage h (8 KB) into chunk-padded smem ----
        const float* src = &g_Hbuf[t & 1][grp][0];
#pragma unroll
        for (int u = 0; u < 2; ++u) {
            int idx = tid + u * RT;            // float4 index 0..511
            int b = idx >> 7, k = (idx & 127) << 2;
            float* dst = Hs + b * BHSTR + (k >> 5) * CHPAD + (k & 31);
            cp16(smem_u32(dst), src + b * HIDDEN + k);
        }
        asm volatile("cp.async.commit_group;");
        asm volatile("cp.async.wait_group 0;");
        __syncthreads();
    }
}

// ---------------------------------------------------------------------------
extern "C" void kernel_launch(void* const* d_in, const int* in_sizes, int n_in,
                              void* d_out, int out_size)
{
    (void)in_sizes; (void)n_in; (void)out_size;
    const float* inputs = (const float*)d_in[0];
    const float* H      = (const float*)d_in[1];
    const float* W_net  = (const float*)d_in[2];
    const float* b_net  = (const float*)d_in[3];
    const float* W_deep = (const float*)d_in[4];
    const float* b_deep = (const float*)d_in[5];

    float* out     = (float*)d_out;
    float* states1 = out;
    float* lasts   = out + (size_t)T_STEPS * BATCH * HIDDEN;

    float *P, *S0;
    cudaGetSymbolAddress((void**)&P,  g_P);
    cudaGetSymbolAddress((void**)&S0, g_S0);

    cudaFuncSetAttribute(rnn_rec, cudaFuncAttributeMaxDynamicSharedMemorySize, REC_SMEM);

    dim3 ggrid(HIDDEN / 128, (T_STEPS * BATCH) / 128);

    gemm_awt<<<ggrid, 256>>>(inputs, W_net, b_net, P, VDIM, VDIM + HIDDEN);
    rnn_rec<<<NB, RT, REC_SMEM>>>(P, W_net, VDIM + HIDDEN, VDIM, H, S0, lasts);

    gemm_awt<<<ggrid, 256>>>(S0, W_deep, b_deep, P, HIDDEN, 2 * HIDDEN);
    rnn_rec<<<NB, RT, REC_SMEM>>>(P, W_deep, 2 * HIDDEN, HIDDEN,
                                  H + BATCH * HIDDEN, states1,
                                  lasts + BATCH * HIDDEN);
}